// round 12
// baseline (speedup 1.0000x reference)
#include <cuda_runtime.h>

// ---------------------------------------------------------------------------
// OverISS_T, R12: byte-exact R9 main kernels (packed f32x2 partials/updates,
// 3-stage packed warp reduce, warp0 mid, two barriers/step, original
// epilogue). Single isolated change vs R9: NCH=29 weight-reduction chunks.
// ---------------------------------------------------------------------------

#define DEVFN __device__ __forceinline__
typedef unsigned long long u64;

namespace cfg {
constexpr int B = 2, C = 6, S = 2, F = 257, N = 1000, T = 5;
constexpr int CB = C - S;
constexpr int PAD = 6;
constexpr int ROW = 1032;
constexpr int NBF = B * F;
constexpr int NT = 256;
constexpr int NCH = 29;
constexpr int FCH = 9;
constexpr float EPS = 1e-3f;
constexpr float MODEL_EPS = 1e-5f;
constexpr float PB_EPS = 1e-6f;
}
using namespace cfg;

// ------------------------- global scratch -------------------------
__device__ float2 gY[B * S * F * N];
__device__ float2 gW[B * F * S * C];
__device__ float2 gH[B * F * S * C * T];
__device__ float2 gCXX[B * F * C * C];
__device__ float2 gCXbX[B * F * C * T * C];
__device__ float  gWt[B * S * N];
__device__ float  gPp[NCH * B * S * N];
__device__ float  gGs[B * S];

// ------------------------- complex helpers -------------------------
DEVFN float2 cmul(float2 a, float2 b) { return make_float2(a.x*b.x - a.y*b.y, a.x*b.y + a.y*b.x); }
DEVFN float2 cadd(float2 a, float2 b) { return make_float2(a.x + b.x, a.y + b.y); }
DEVFN float2 csub(float2 a, float2 b) { return make_float2(a.x - b.x, a.y - b.y); }
DEVFN float2 conjf2(float2 a)         { return make_float2(a.x, -a.y); }
DEVFN float2 cdiv(float2 a, float2 b) {
    float d = b.x*b.x + b.y*b.y;
    return make_float2((a.x*b.x + a.y*b.y) / d, (a.y*b.x - a.x*b.y) / d);
}

// ------------------------- packed f32x2 helpers (sm_103a) -------------------------
DEVFN u64 pk2(float lo, float hi) {
    u64 r; asm("mov.b64 %0, {%1, %2};" : "=l"(r) : "f"(lo), "f"(hi)); return r;
}
DEVFN void up2(u64 v, float& lo, float& hi) {
    asm("mov.b64 {%0, %1}, %2;" : "=f"(lo), "=f"(hi) : "l"(v));
}
DEVFN u64 f2mul(u64 a, u64 b) {
    u64 r; asm("mul.rn.f32x2 %0, %1, %2;" : "=l"(r) : "l"(a), "l"(b)); return r;
}
DEVFN u64 f2fma(u64 a, u64 b, u64 c) {
    u64 r; asm("fma.rn.f32x2 %0, %1, %2, %3;" : "=l"(r) : "l"(a), "l"(b), "l"(c)); return r;
}
DEVFN u64 f2add(u64 a, u64 b) {
    u64 r; asm("add.rn.f32x2 %0, %1, %2;" : "=l"(r) : "l"(a), "l"(b)); return r;
}
DEVFN u64 shfl64(u64 v, int off) {
    return __shfl_down_sync(0xffffffffu, v, off);
}

DEVFN void load_Xpad(float2* Xs, const float* __restrict__ Xr,
                     const float* __restrict__ Xi, int b, int f, int tid) {
    for (int i = tid; i < C * ROW; i += NT) {
        int d = i / ROW, j = i % ROW;
        float2 v = make_float2(0.f, 0.f);
        if (j >= PAD && j < PAD + N) {
            int gi = ((b * C + d) * F + f) * N + (j - PAD);
            v = make_float2(Xr[gi], Xi[gi]);
        }
        Xs[i] = v;
    }
}

DEVFN void bg_update(const float2* sW, const float2* sH, const float2* sXX,
                     const float2* sXbX, float2* sA, int tid) {
    if (tid < S * C) {
        int s = tid / C, d = tid % C;
        float2 acc = make_float2(0.f, 0.f);
        for (int c = 0; c < C; c++) acc = cadd(acc, cmul(sW[s * C + c], sXX[c * C + d]));
        for (int dd = 0; dd < C; dd++)
#pragma unroll
            for (int t = 0; t < T; t++)
                acc = cadd(acc, cmul(sH[(s * C + dd) * T + t], sXbX[(dd * T + t) * C + d]));
        sA[s * C + d] = acc;
    }
}

DEVFN void solveJ(const float2* sA, float2* sJ) {
    float2 M00 = sA[0], M01 = sA[1], M10 = sA[C], M11 = sA[C + 1];
    float2 det = csub(cmul(M00, M11), cmul(M01, M10));
#pragma unroll
    for (int k = 0; k < CB; k++) {
        float2 r0 = sA[2 + k], r1 = sA[C + 2 + k];
        float2 jh0 = cdiv(csub(cmul(M11, r0), cmul(M01, r1)), det);
        float2 jh1 = cdiv(csub(cmul(M00, r1), cmul(M10, r0)), det);
        sJ[k * S + 0] = conjf2(jh0);
        sJ[k * S + 1] = conjf2(jh1);
    }
}

// One ISS step on source-packed Y. Packed 3-stage warp reduce, lanes 0-3
// store u64 partials; warp0 does packed 5-stage 32-wide reduce in the mid.
template <int MODE>
DEVFN void iss_core(const float2 (&xv)[4], u64 (&ya)[4], u64 (&yb)[4],
                    const u64 (&w01)[4],
                    float2* sW, float2* sH, const float2* sJ,
                    u64* red64, float2* sv,
                    int tid, int warp, int lane, int idx) {
    u64 s03 = 0ull, s14 = 0ull, s25 = 0ull;
#pragma unroll
    for (int i = 0; i < 4; i++) {
        float2 x = xv[i];
        u64 xx = pk2(x.x, x.x);
        u64 xy = pk2(x.y, x.y);
        float nx = -x.y;
        u64 nxy = pk2(nx, nx);
        u64 re = f2fma(yb[i], xy, f2mul(ya[i], xx));
        u64 im = f2fma(ya[i], nxy, f2mul(yb[i], xx));
        s03 = f2fma(w01[i], re, s03);
        s14 = f2fma(w01[i], im, s14);
        float mm = fmaf(x.y, x.y, x.x * x.x);
        s25 = f2fma(w01[i], pk2(mm, mm), s25);
    }
#pragma unroll
    for (int off = 16; off >= 4; off >>= 1) {
        s03 = f2add(s03, shfl64(s03, off));
        s14 = f2add(s14, shfl64(s14, off));
        s25 = f2add(s25, shfl64(s25, off));
    }
    if (lane < 4) {
        int slot = warp * 4 + lane;
        red64[0 * 32 + slot] = s03;
        red64[1 * 32 + slot] = s14;
        red64[2 * 32 + slot] = s25;
    }
    __syncthreads();
    if (warp == 0) {
        u64 a = red64[lane], b = red64[32 + lane], c = red64[64 + lane];
#pragma unroll
        for (int off = 16; off >= 1; off >>= 1) {
            a = f2add(a, shfl64(a, off));
            b = f2add(b, shfl64(b, off));
            c = f2add(c, shfl64(c, off));
        }
        if (lane == 0) {
            float t0, t1, t2, t3, t4, t5;
            up2(a, t0, t3); up2(b, t1, t4); up2(c, t2, t5);
            if (MODE == 0) {
                const float invN = 1.f / (float)N;
                t0 *= invN; t1 *= invN; t2 *= invN;
                t3 *= invN; t4 *= invN; t5 *= invN;
            }
            float d0 = fmaxf(t2, EPS), d1 = fmaxf(t5, EPS);
            float2 v0 = make_float2(t0 / d0, t1 / d0);
            float2 v1 = make_float2(t3 / d1, t4 / d1);
            if (MODE == 0) {
                float ds = (idx == 0) ? t2 : t5;
                float vs = 1.f - 1.f / sqrtf(fmaxf(ds, EPS));
                if (idx == 0) v0 = make_float2(vs, 0.f);
                else          v1 = make_float2(vs, 0.f);
            }
            sv[0] = v0; sv[1] = v1;
        }
    }
    __syncthreads();
    float2 v0 = sv[0], v1 = sv[1];
    u64 nvx = pk2(-v0.x, -v1.x);
    u64 vvy = pk2(v0.y, v1.y);
    u64 nvy = pk2(-v0.y, -v1.y);
#pragma unroll
    for (int i = 0; i < 4; i++) {
        float2 x = xv[i];
        u64 xx = pk2(x.x, x.x);
        u64 xy = pk2(x.y, x.y);
        ya[i] = f2fma(vvy, xy, f2fma(nvx, xx, ya[i]));
        yb[i] = f2fma(nvy, xx, f2fma(nvx, xy, yb[i]));
    }
    if (MODE == 0) {
        if (tid < C) {
            float2 a = sW[idx * C + tid];
            sW[tid]     = csub(sW[tid],     cmul(v0, a));
            sW[C + tid] = csub(sW[C + tid], cmul(v1, a));
        } else if (tid >= 32 && tid < 32 + C * T) {
            int j = tid - 32;
            float2 a = sH[idx * C * T + j];
            sH[j]         = csub(sH[j],         cmul(v0, a));
            sH[C * T + j] = csub(sH[C * T + j], cmul(v1, a));
        }
    } else if (MODE == 1) {
        if (tid < 2) {
            float2 v = tid ? v1 : v0;
            sW[tid * C + 0]       = csub(sW[tid * C + 0], cmul(v, sJ[idx * S + 0]));
            sW[tid * C + 1]       = csub(sW[tid * C + 1], cmul(v, sJ[idx * S + 1]));
            sW[tid * C + S + idx] = cadd(sW[tid * C + S + idx], v);
        }
    } else {
        if (tid < 2) {
            float2 v = tid ? v1 : v0;
            int d = idx / T, tp = idx % T;
            sH[(tid * C + d) * T + tp] = cadd(sH[(tid * C + d) * T + tp], v);
        }
    }
}

DEVFN void run_steps(const float2* Xs, float2* sW, float2* sH, const float2* sJ,
                     u64* red64, float2* sv, u64 (&ya)[4], u64 (&yb)[4],
                     const u64 (&w01)[4],
                     int tid, int warp, int lane) {
#pragma unroll 1
    for (int src = 0; src < S; src++) {
        float2 xv[4];
#pragma unroll
        for (int i = 0; i < 4; i++) {
            float a, c, bb, d;
            up2(ya[i], a, c);
            up2(yb[i], bb, d);
            xv[i] = src ? make_float2(c, d) : make_float2(a, bb);
        }
        iss_core<0>(xv, ya, yb, w01, sW, sH, sJ, red64, sv, tid, warp, lane, src);
    }
#pragma unroll 1
    for (int k = 0; k < CB; k++) {
        float2 j0 = sJ[k * S + 0], j1 = sJ[k * S + 1];
        float2 xv[4];
#pragma unroll
        for (int i = 0; i < 4; i++) {
            int n = tid + i * NT;
            float2 x0 = Xs[0 * ROW + PAD + n];
            float2 x1 = Xs[ROW + PAD + n];
            float2 xb = Xs[(S + k) * ROW + PAD + n];
            xv[i] = csub(cadd(cmul(j0, x0), cmul(j1, x1)), xb);
        }
        iss_core<1>(xv, ya, yb, w01, sW, sH, sJ, red64, sv, tid, warp, lane, k);
    }
#pragma unroll 1
    for (int q = 0; q < C * T; q++) {
        const float2* xp = Xs + (q / T) * ROW + (q % T);
        float2 xv[4];
#pragma unroll
        for (int i = 0; i < 4; i++) xv[i] = xp[tid + i * NT];
        iss_core<2>(xv, ya, yb, w01, sW, sH, sJ, red64, sv, tid, warp, lane, q);
    }
}

// ===========================================================================
// Weight reduction: NCH=29 f-chunks, MLP-8 batched loads
// ===========================================================================
__global__ void __launch_bounds__(128) k_ps0(const float* __restrict__ Xr,
                                             const float* __restrict__ Xi) {
    const int tid = threadIdx.x;
    if (tid >= 125) return;
    const int n = blockIdx.x * 125 + tid;
    const int bs = blockIdx.y;
    const int ch = blockIdx.z;
    const int b = bs / S, s = bs % S;
    const size_t base = ((size_t)(b * C + s) * F) * N + n;
    const int f0 = ch * FCH;
    const int nf = ((f0 + FCH <= F) ? FCH : F - f0);
    float acc[8];
#pragma unroll
    for (int j = 0; j < 8; j++) acc[j] = 0.f;
    const int full = nf & ~7;
#pragma unroll 1
    for (int fb = 0; fb < full; fb += 8) {
        float r[8], im[8];
#pragma unroll
        for (int j = 0; j < 8; j++) {
            size_t p = base + (size_t)(f0 + fb + j) * N;
            r[j] = Xr[p];
            im[j] = Xi[p];
        }
#pragma unroll
        for (int j = 0; j < 8; j++) acc[j] += r[j] * r[j] + im[j] * im[j];
    }
    for (int f = full; f < nf; f++) {
        size_t p = base + (size_t)(f0 + f) * N;
        float r = Xr[p], im = Xi[p];
        acc[0] += r * r + im * im;
    }
    gPp[(ch * B * S + bs) * N + n] =
        ((acc[0] + acc[1]) + (acc[2] + acc[3])) + ((acc[4] + acc[5]) + (acc[6] + acc[7]));
}

__global__ void __launch_bounds__(128) k_psY() {
    const int tid = threadIdx.x;
    if (tid >= 125) return;
    const int n = blockIdx.x * 125 + tid;
    const int bs = blockIdx.y;
    const int ch = blockIdx.z;
    const float2* py = gY + (size_t)bs * F * N + n;
    const int f0 = ch * FCH;
    const int nf = ((f0 + FCH <= F) ? FCH : F - f0);
    float acc[8];
#pragma unroll
    for (int j = 0; j < 8; j++) acc[j] = 0.f;
    const int full = nf & ~7;
#pragma unroll 1
    for (int fb = 0; fb < full; fb += 8) {
        float2 v[8];
#pragma unroll
        for (int j = 0; j < 8; j++) v[j] = py[(size_t)(f0 + fb + j) * N];
#pragma unroll
        for (int j = 0; j < 8; j++) acc[j] += v[j].x * v[j].x + v[j].y * v[j].y;
    }
    for (int f = full; f < nf; f++) {
        float2 v = py[(size_t)(f0 + f) * N];
        acc[0] += v.x * v.x + v.y * v.y;
    }
    gPp[(ch * B * S + bs) * N + n] =
        ((acc[0] + acc[1]) + (acc[2] + acc[3])) + ((acc[4] + acc[5]) + (acc[6] + acc[7]));
}

__global__ void __launch_bounds__(256) k_wt() {
    const int bs = blockIdx.x;
    const int tid = threadIdx.x;
    float p[4];
    float s = 0.f;
#pragma unroll
    for (int i = 0; i < 4; i++) {
        int n = tid + i * 256;
        float acc = 0.f;
        if (n < N) {
#pragma unroll 1
            for (int ch = 0; ch < NCH; ch++) acc += gPp[(ch * B * S + bs) * N + n];
        }
        p[i] = acc;
        s += acc;
    }
    __shared__ float rr[8];
    __shared__ float g_sh;
#pragma unroll
    for (int off = 16; off > 0; off >>= 1) s += __shfl_down_sync(0xffffffffu, s, off);
    if ((tid & 31) == 0) rr[tid >> 5] = s;
    __syncthreads();
    if (tid == 0) {
        float tot = 0.f;
        for (int w = 0; w < 8; w++) tot += rr[w];
        float g = fmaxf(tot / (float)(F * N), EPS);
        g_sh = g;
        gGs[bs] = sqrtf(g);
    }
    __syncthreads();
    float g = g_sh;
#pragma unroll
    for (int i = 0; i < 4; i++) {
        int n = tid + i * 256;
        if (n < N) gWt[bs * N + n] = g / fmaxf(2.f * sqrtf(p[i]), MODEL_EPS);
    }
}

// ===========================================================================
// k_first: covariances + iteration 1
// ===========================================================================
__global__ void __launch_bounds__(NT, 4) k_first(const float* __restrict__ Xr,
                                                 const float* __restrict__ Xi) {
    extern __shared__ float2 sm1[];
    float2* Xs   = sm1;
    float2* sW   = Xs + C * ROW;
    float2* sH   = sW + S * C;
    float2* sJ   = sH + S * C * T;
    float2* sA   = sJ + CB * S;
    float2* sXX  = sA + S * C;
    float2* sXbX = sXX + C * C;
    float2* sv   = sXbX + C * T * C;            // 2
    u64*    red64 = (u64*)(sv + 2);             // 96 u64

    const int bf = blockIdx.x;
    const int b = bf / F, f = bf % F;
    const int tid = threadIdx.x;
    const int warp = tid >> 5, lane = tid & 31;

    load_Xpad(Xs, Xr, Xi, b, f, tid);

    const float i0 = 1.f / gGs[b * S + 0];
    const float i1 = 1.f / gGs[b * S + 1];

    if (tid < S * C) {
        int s = tid / C, c = tid % C;
        sW[tid] = make_float2((s == c) ? ((s == 0) ? i0 : i1) : 0.f, 0.f);
    }
    if (tid < S * C * T) sH[tid] = make_float2(0.f, 0.f);
    __syncthreads();

#define ACCP(j, A, Bv) { ar[j] += (A).x*(Bv).x + (A).y*(Bv).y; \
                         ai[j] += (A).y*(Bv).x - (A).x*(Bv).y; }
#pragma unroll 1
    for (int g = warp; g < 18; g += NT / 32) {
        int d = g / 3, p = g % 3, c0 = 2 * p;
        const float2* ad = Xs + d * ROW;
        const float2* b0 = Xs + c0 * ROW + PAD;
        const float2* b1 = b0 + ROW;
        float ar[12], ai[12];
#pragma unroll
        for (int j = 0; j < 12; j++) { ar[j] = 0.f; ai[j] = 0.f; }
        for (int n = lane; n < N; n += 32) {
            float2 a0 = ad[n], a1 = ad[n+1], a2 = ad[n+2], a3 = ad[n+3], a4 = ad[n+4];
            float2 a6 = ad[n+6];
            float2 u = b0[n], v = b1[n];
            ACCP(0, a0, u); ACCP(1, a1, u); ACCP(2, a2, u); ACCP(3, a3, u); ACCP(4, a4, u);
            ACCP(5, a0, v); ACCP(6, a1, v); ACCP(7, a2, v); ACCP(8, a3, v); ACCP(9, a4, v);
            ACCP(10, u, a6); ACCP(11, v, a6);
        }
#pragma unroll
        for (int off = 16; off > 0; off >>= 1)
#pragma unroll
            for (int j = 0; j < 12; j++) {
                ar[j] += __shfl_down_sync(0xffffffffu, ar[j], off);
                ai[j] += __shfl_down_sync(0xffffffffu, ai[j], off);
            }
        if (lane == 0) {
            const float invN = 1.f / (float)N;
#pragma unroll
            for (int t = 0; t < T; t++) {
                float2 v0 = make_float2(ar[t] * invN, ai[t] * invN);
                float2 v1 = make_float2(ar[5 + t] * invN, ai[5 + t] * invN);
                sXbX[(d * T + t) * C + c0]     = v0;
                sXbX[(d * T + t) * C + c0 + 1] = v1;
                gCXbX[bf * C * T * C + (d * T + t) * C + c0]     = v0;
                gCXbX[bf * C * T * C + (d * T + t) * C + c0 + 1] = v1;
            }
            float2 x0 = make_float2(ar[10] * invN, ai[10] * invN);
            float2 x1 = make_float2(ar[11] * invN, ai[11] * invN);
            sXX[c0 * C + d]       = x0;
            sXX[(c0 + 1) * C + d] = x1;
            gCXX[bf * C * C + c0 * C + d]       = x0;
            gCXX[bf * C * C + (c0 + 1) * C + d] = x1;
        }
    }
#undef ACCP

    u64 ya[4], yb[4], w01[4];
#pragma unroll
    for (int i = 0; i < 4; i++) {
        int n = tid + i * NT;
        if (n < N) {
            float2 a = Xs[0 * ROW + PAD + n];
            float2 c = Xs[1 * ROW + PAD + n];
            ya[i] = pk2(a.x * i0, c.x * i1);
            yb[i] = pk2(a.y * i0, c.y * i1);
            w01[i] = pk2(gWt[(b * S + 0) * N + n], gWt[(b * S + 1) * N + n]);
        } else {
            ya[i] = yb[i] = w01[i] = 0ull;
        }
    }
    __syncthreads();

    bg_update(sW, sH, sXX, sXbX, sA, tid);
    __syncthreads();
    if (tid == 0) solveJ(sA, sJ);
    __syncthreads();

    run_steps(Xs, sW, sH, sJ, red64, sv, ya, yb, w01, tid, warp, lane);
    __syncthreads();

#pragma unroll
    for (int i = 0; i < 4; i++) {
        int n = tid + i * NT;
        if (n < N) {
            float a, c, bb, d;
            up2(ya[i], a, c);
            up2(yb[i], bb, d);
            gY[((b * S + 0) * F + f) * N + n] = make_float2(a, bb);
            gY[((b * S + 1) * F + f) * N + n] = make_float2(c, d);
        }
    }
    if (tid < S * C) gW[bf * S * C + tid] = sW[tid];
    if (tid < S * C * T) gH[bf * S * C * T + tid] = sH[tid];
}

// ===========================================================================
// k_last: iteration 2 + final J + demix/derev + projection back + output
// ===========================================================================
__global__ void __launch_bounds__(NT, 4) k_last(const float* __restrict__ Xr,
                                                const float* __restrict__ Xi,
                                                float* __restrict__ out) {
    extern __shared__ float2 sm2[];
    float2* Xs   = sm2;
    float2* sW   = Xs + C * ROW;
    float2* sH   = sW + S * C;
    float2* sJ   = sH + S * C * T;
    float2* sA   = sJ + CB * S;
    float2* sXX  = sA + S * C;
    float2* sXbX = sXX + C * C;
    float2* sv   = sXbX + C * T * C;
    u64*    red64 = (u64*)(sv + 2);

    const int bf = blockIdx.x;
    const int b = bf / F, f = bf % F;
    const int tid = threadIdx.x;
    const int warp = tid >> 5, lane = tid & 31;

    load_Xpad(Xs, Xr, Xi, b, f, tid);

    const float i0 = 1.f / gGs[b * S + 0];
    const float i1 = 1.f / gGs[b * S + 1];

    if (tid < S * C) {
        float iv = (tid < C) ? i0 : i1;
        float2 w = gW[bf * S * C + tid];
        sW[tid] = make_float2(w.x * iv, w.y * iv);
    }
    if (tid < S * C * T) {
        float iv = (tid < C * T) ? i0 : i1;
        float2 h = gH[bf * S * C * T + tid];
        sH[tid] = make_float2(h.x * iv, h.y * iv);
    }
    if (tid < C * C) sXX[tid] = gCXX[bf * C * C + tid];
    if (tid < C * T * C) sXbX[tid] = gCXbX[bf * C * T * C + tid];

    u64 ya[4], yb[4], w01[4];
#pragma unroll
    for (int i = 0; i < 4; i++) {
        int n = tid + i * NT;
        if (n < N) {
            float2 a = gY[((b * S + 0) * F + f) * N + n];
            float2 c = gY[((b * S + 1) * F + f) * N + n];
            ya[i] = pk2(a.x * i0, c.x * i1);
            yb[i] = pk2(a.y * i0, c.y * i1);
            w01[i] = pk2(gWt[(b * S + 0) * N + n], gWt[(b * S + 1) * N + n]);
        } else {
            ya[i] = yb[i] = w01[i] = 0ull;
        }
    }
    __syncthreads();

    bg_update(sW, sH, sXX, sXbX, sA, tid);
    __syncthreads();
    if (tid == 0) solveJ(sA, sJ);
    __syncthreads();

    run_steps(Xs, sW, sH, sJ, red64, sv, ya, yb, w01, tid, warp, lane);
    __syncthreads();

    bg_update(sW, sH, sXX, sXbX, sA, tid);
    __syncthreads();
    if (tid == 0) {
        solveJ(sA, sJ);
        float2 Bm[2][2];
#pragma unroll
        for (int s = 0; s < S; s++)
#pragma unroll
            for (int k = 0; k < S; k++) {
                float2 acc = sW[s * C + k];
                for (int c = 0; c < CB; c++)
                    acc = cadd(acc, cmul(sW[s * C + S + c], sJ[c * S + k]));
                Bm[s][k] = acc;
            }
        float2 P00 = make_float2(Bm[0][0].x + PB_EPS, Bm[0][0].y);
        float2 P01 = Bm[1][0];
        float2 P10 = Bm[0][1];
        float2 P11 = make_float2(Bm[1][1].x + PB_EPS, Bm[1][1].y);
        float2 pdet = csub(cmul(P00, P11), cmul(P01, P10));
        sA[0] = cdiv(P11, pdet);
        sA[1] = cdiv(make_float2(-P10.x, -P10.y), pdet);
    }
    __syncthreads();

    float2 a0 = sA[0], a1 = sA[1];
    for (int n = tid; n < N; n += NT) {
#pragma unroll
        for (int s = 0; s < S; s++) {
            float2 y = make_float2(0.f, 0.f);
            for (int d = 0; d < C; d++) {
                const float2* xr = Xs + d * ROW + n;
                y = cadd(y, cmul(sW[s * C + d], xr[PAD]));
#pragma unroll
                for (int t = 0; t < T; t++)
                    y = csub(y, cmul(sH[(s * C + d) * T + t], xr[t]));
            }
            y = cmul(y, (s == 0) ? a0 : a1);
            size_t oi = ((size_t)((b * S + s) * F + f) * N + n) * 2;
            out[oi]     = y.x;
            out[oi + 1] = y.y;
        }
    }
}

// ===========================================================================
// launch
// ===========================================================================
namespace {
constexpr size_t SMEM_MAIN = sizeof(float2) * (size_t)(C * ROW + S * C + S * C * T +
                                                       CB * S + S * C + C * C + C * T * C + 2)
                           + sizeof(u64) * 96;
}

extern "C" void kernel_launch(void* const* d_in, const int* in_sizes, int n_in,
                              void* d_out, int out_size) {
    (void)in_sizes; (void)n_in; (void)out_size;
    const float* Xr = (const float*)d_in[0];
    const float* Xi = (const float*)d_in[1];
    float* out = (float*)d_out;

    cudaFuncSetAttribute(k_first, cudaFuncAttributeMaxDynamicSharedMemorySize, (int)SMEM_MAIN);
    cudaFuncSetAttribute(k_last,  cudaFuncAttributeMaxDynamicSharedMemorySize, (int)SMEM_MAIN);

    k_ps0<<<dim3(8, B * S, NCH), 128>>>(Xr, Xi);
    k_wt<<<B * S, 256>>>();
    k_first<<<NBF, NT, SMEM_MAIN>>>(Xr, Xi);
    k_psY<<<dim3(8, B * S, NCH), 128>>>();
    k_wt<<<B * S, 256>>>();
    k_last<<<NBF, NT, SMEM_MAIN>>>(Xr, Xi, out);
}

// round 13
// speedup vs baseline: 1.9598x; 1.9598x over previous
#include <cuda_runtime.h>

// ---------------------------------------------------------------------------
// OverISS_T, R13: byte-exact resubmission of R9 (best measured: 177.3 us)
// to re-validate the baseline after the non-credible R12 measurement.
// Packed f32x2 partials/updates, 3-stage packed warp reduce, warp0 mid,
// two barriers per step, NCH=16 weight reduction.
// ---------------------------------------------------------------------------

#define DEVFN __device__ __forceinline__
typedef unsigned long long u64;

namespace cfg {
constexpr int B = 2, C = 6, S = 2, F = 257, N = 1000, T = 5;
constexpr int CB = C - S;
constexpr int PAD = 6;
constexpr int ROW = 1032;
constexpr int NBF = B * F;
constexpr int NT = 256;
constexpr int NCH = 16;
constexpr int FCH = 17;
constexpr float EPS = 1e-3f;
constexpr float MODEL_EPS = 1e-5f;
constexpr float PB_EPS = 1e-6f;
}
using namespace cfg;

// ------------------------- global scratch -------------------------
__device__ float2 gY[B * S * F * N];
__device__ float2 gW[B * F * S * C];
__device__ float2 gH[B * F * S * C * T];
__device__ float2 gCXX[B * F * C * C];
__device__ float2 gCXbX[B * F * C * T * C];
__device__ float  gWt[B * S * N];
__device__ float  gPp[NCH * B * S * N];
__device__ float  gGs[B * S];

// ------------------------- complex helpers -------------------------
DEVFN float2 cmul(float2 a, float2 b) { return make_float2(a.x*b.x - a.y*b.y, a.x*b.y + a.y*b.x); }
DEVFN float2 cadd(float2 a, float2 b) { return make_float2(a.x + b.x, a.y + b.y); }
DEVFN float2 csub(float2 a, float2 b) { return make_float2(a.x - b.x, a.y - b.y); }
DEVFN float2 conjf2(float2 a)         { return make_float2(a.x, -a.y); }
DEVFN float2 cdiv(float2 a, float2 b) {
    float d = b.x*b.x + b.y*b.y;
    return make_float2((a.x*b.x + a.y*b.y) / d, (a.y*b.x - a.x*b.y) / d);
}

// ------------------------- packed f32x2 helpers (sm_103a) -------------------------
DEVFN u64 pk2(float lo, float hi) {
    u64 r; asm("mov.b64 %0, {%1, %2};" : "=l"(r) : "f"(lo), "f"(hi)); return r;
}
DEVFN void up2(u64 v, float& lo, float& hi) {
    asm("mov.b64 {%0, %1}, %2;" : "=f"(lo), "=f"(hi) : "l"(v));
}
DEVFN u64 f2mul(u64 a, u64 b) {
    u64 r; asm("mul.rn.f32x2 %0, %1, %2;" : "=l"(r) : "l"(a), "l"(b)); return r;
}
DEVFN u64 f2fma(u64 a, u64 b, u64 c) {
    u64 r; asm("fma.rn.f32x2 %0, %1, %2, %3;" : "=l"(r) : "l"(a), "l"(b), "l"(c)); return r;
}
DEVFN u64 f2add(u64 a, u64 b) {
    u64 r; asm("add.rn.f32x2 %0, %1, %2;" : "=l"(r) : "l"(a), "l"(b)); return r;
}
DEVFN u64 shfl64(u64 v, int off) {
    return __shfl_down_sync(0xffffffffu, v, off);
}

DEVFN void load_Xpad(float2* Xs, const float* __restrict__ Xr,
                     const float* __restrict__ Xi, int b, int f, int tid) {
    for (int i = tid; i < C * ROW; i += NT) {
        int d = i / ROW, j = i % ROW;
        float2 v = make_float2(0.f, 0.f);
        if (j >= PAD && j < PAD + N) {
            int gi = ((b * C + d) * F + f) * N + (j - PAD);
            v = make_float2(Xr[gi], Xi[gi]);
        }
        Xs[i] = v;
    }
}

DEVFN void bg_update(const float2* sW, const float2* sH, const float2* sXX,
                     const float2* sXbX, float2* sA, int tid) {
    if (tid < S * C) {
        int s = tid / C, d = tid % C;
        float2 acc = make_float2(0.f, 0.f);
        for (int c = 0; c < C; c++) acc = cadd(acc, cmul(sW[s * C + c], sXX[c * C + d]));
        for (int dd = 0; dd < C; dd++)
#pragma unroll
            for (int t = 0; t < T; t++)
                acc = cadd(acc, cmul(sH[(s * C + dd) * T + t], sXbX[(dd * T + t) * C + d]));
        sA[s * C + d] = acc;
    }
}

DEVFN void solveJ(const float2* sA, float2* sJ) {
    float2 M00 = sA[0], M01 = sA[1], M10 = sA[C], M11 = sA[C + 1];
    float2 det = csub(cmul(M00, M11), cmul(M01, M10));
#pragma unroll
    for (int k = 0; k < CB; k++) {
        float2 r0 = sA[2 + k], r1 = sA[C + 2 + k];
        float2 jh0 = cdiv(csub(cmul(M11, r0), cmul(M01, r1)), det);
        float2 jh1 = cdiv(csub(cmul(M00, r1), cmul(M10, r0)), det);
        sJ[k * S + 0] = conjf2(jh0);
        sJ[k * S + 1] = conjf2(jh1);
    }
}

// One ISS step on source-packed Y. Packed 3-stage warp reduce, lanes 0-3
// store u64 partials; warp0 does packed 5-stage 32-wide reduce in the mid.
template <int MODE>
DEVFN void iss_core(const float2 (&xv)[4], u64 (&ya)[4], u64 (&yb)[4],
                    const u64 (&w01)[4],
                    float2* sW, float2* sH, const float2* sJ,
                    u64* red64, float2* sv,
                    int tid, int warp, int lane, int idx) {
    u64 s03 = 0ull, s14 = 0ull, s25 = 0ull;
#pragma unroll
    for (int i = 0; i < 4; i++) {
        float2 x = xv[i];
        u64 xx = pk2(x.x, x.x);
        u64 xy = pk2(x.y, x.y);
        float nx = -x.y;
        u64 nxy = pk2(nx, nx);
        u64 re = f2fma(yb[i], xy, f2mul(ya[i], xx));
        u64 im = f2fma(ya[i], nxy, f2mul(yb[i], xx));
        s03 = f2fma(w01[i], re, s03);
        s14 = f2fma(w01[i], im, s14);
        float mm = fmaf(x.y, x.y, x.x * x.x);
        s25 = f2fma(w01[i], pk2(mm, mm), s25);
    }
#pragma unroll
    for (int off = 16; off >= 4; off >>= 1) {
        s03 = f2add(s03, shfl64(s03, off));
        s14 = f2add(s14, shfl64(s14, off));
        s25 = f2add(s25, shfl64(s25, off));
    }
    if (lane < 4) {
        int slot = warp * 4 + lane;
        red64[0 * 32 + slot] = s03;
        red64[1 * 32 + slot] = s14;
        red64[2 * 32 + slot] = s25;
    }
    __syncthreads();
    if (warp == 0) {
        u64 a = red64[lane], b = red64[32 + lane], c = red64[64 + lane];
#pragma unroll
        for (int off = 16; off >= 1; off >>= 1) {
            a = f2add(a, shfl64(a, off));
            b = f2add(b, shfl64(b, off));
            c = f2add(c, shfl64(c, off));
        }
        if (lane == 0) {
            float t0, t1, t2, t3, t4, t5;
            up2(a, t0, t3); up2(b, t1, t4); up2(c, t2, t5);
            if (MODE == 0) {
                const float invN = 1.f / (float)N;
                t0 *= invN; t1 *= invN; t2 *= invN;
                t3 *= invN; t4 *= invN; t5 *= invN;
            }
            float d0 = fmaxf(t2, EPS), d1 = fmaxf(t5, EPS);
            float2 v0 = make_float2(t0 / d0, t1 / d0);
            float2 v1 = make_float2(t3 / d1, t4 / d1);
            if (MODE == 0) {
                float ds = (idx == 0) ? t2 : t5;
                float vs = 1.f - 1.f / sqrtf(fmaxf(ds, EPS));
                if (idx == 0) v0 = make_float2(vs, 0.f);
                else          v1 = make_float2(vs, 0.f);
            }
            sv[0] = v0; sv[1] = v1;
        }
    }
    __syncthreads();
    float2 v0 = sv[0], v1 = sv[1];
    u64 nvx = pk2(-v0.x, -v1.x);
    u64 vvy = pk2(v0.y, v1.y);
    u64 nvy = pk2(-v0.y, -v1.y);
#pragma unroll
    for (int i = 0; i < 4; i++) {
        float2 x = xv[i];
        u64 xx = pk2(x.x, x.x);
        u64 xy = pk2(x.y, x.y);
        ya[i] = f2fma(vvy, xy, f2fma(nvx, xx, ya[i]));
        yb[i] = f2fma(nvy, xx, f2fma(nvx, xy, yb[i]));
    }
    if (MODE == 0) {
        if (tid < C) {
            float2 a = sW[idx * C + tid];
            sW[tid]     = csub(sW[tid],     cmul(v0, a));
            sW[C + tid] = csub(sW[C + tid], cmul(v1, a));
        } else if (tid >= 32 && tid < 32 + C * T) {
            int j = tid - 32;
            float2 a = sH[idx * C * T + j];
            sH[j]         = csub(sH[j],         cmul(v0, a));
            sH[C * T + j] = csub(sH[C * T + j], cmul(v1, a));
        }
    } else if (MODE == 1) {
        if (tid < 2) {
            float2 v = tid ? v1 : v0;
            sW[tid * C + 0]       = csub(sW[tid * C + 0], cmul(v, sJ[idx * S + 0]));
            sW[tid * C + 1]       = csub(sW[tid * C + 1], cmul(v, sJ[idx * S + 1]));
            sW[tid * C + S + idx] = cadd(sW[tid * C + S + idx], v);
        }
    } else {
        if (tid < 2) {
            float2 v = tid ? v1 : v0;
            int d = idx / T, tp = idx % T;
            sH[(tid * C + d) * T + tp] = cadd(sH[(tid * C + d) * T + tp], v);
        }
    }
}

DEVFN void run_steps(const float2* Xs, float2* sW, float2* sH, const float2* sJ,
                     u64* red64, float2* sv, u64 (&ya)[4], u64 (&yb)[4],
                     const u64 (&w01)[4],
                     int tid, int warp, int lane) {
#pragma unroll 1
    for (int src = 0; src < S; src++) {
        float2 xv[4];
#pragma unroll
        for (int i = 0; i < 4; i++) {
            float a, c, bb, d;
            up2(ya[i], a, c);
            up2(yb[i], bb, d);
            xv[i] = src ? make_float2(c, d) : make_float2(a, bb);
        }
        iss_core<0>(xv, ya, yb, w01, sW, sH, sJ, red64, sv, tid, warp, lane, src);
    }
#pragma unroll 1
    for (int k = 0; k < CB; k++) {
        float2 j0 = sJ[k * S + 0], j1 = sJ[k * S + 1];
        float2 xv[4];
#pragma unroll
        for (int i = 0; i < 4; i++) {
            int n = tid + i * NT;
            float2 x0 = Xs[0 * ROW + PAD + n];
            float2 x1 = Xs[ROW + PAD + n];
            float2 xb = Xs[(S + k) * ROW + PAD + n];
            xv[i] = csub(cadd(cmul(j0, x0), cmul(j1, x1)), xb);
        }
        iss_core<1>(xv, ya, yb, w01, sW, sH, sJ, red64, sv, tid, warp, lane, k);
    }
#pragma unroll 1
    for (int q = 0; q < C * T; q++) {
        const float2* xp = Xs + (q / T) * ROW + (q % T);
        float2 xv[4];
#pragma unroll
        for (int i = 0; i < 4; i++) xv[i] = xp[tid + i * NT];
        iss_core<2>(xv, ya, yb, w01, sW, sH, sJ, red64, sv, tid, warp, lane, q);
    }
}

// ===========================================================================
// Weight reduction: NCH f-chunks, MLP-8 batched loads
// ===========================================================================
__global__ void __launch_bounds__(128) k_ps0(const float* __restrict__ Xr,
                                             const float* __restrict__ Xi) {
    const int tid = threadIdx.x;
    if (tid >= 125) return;
    const int n = blockIdx.x * 125 + tid;
    const int bs = blockIdx.y;
    const int ch = blockIdx.z;
    const int b = bs / S, s = bs % S;
    const size_t base = ((size_t)(b * C + s) * F) * N + n;
    const int f0 = ch * FCH;
    const int nf = ((f0 + FCH <= F) ? FCH : F - f0);
    float acc[8];
#pragma unroll
    for (int j = 0; j < 8; j++) acc[j] = 0.f;
    const int full = nf & ~7;
#pragma unroll 1
    for (int fb = 0; fb < full; fb += 8) {
        float r[8], im[8];
#pragma unroll
        for (int j = 0; j < 8; j++) {
            size_t p = base + (size_t)(f0 + fb + j) * N;
            r[j] = Xr[p];
            im[j] = Xi[p];
        }
#pragma unroll
        for (int j = 0; j < 8; j++) acc[j] += r[j] * r[j] + im[j] * im[j];
    }
    for (int f = full; f < nf; f++) {
        size_t p = base + (size_t)(f0 + f) * N;
        float r = Xr[p], im = Xi[p];
        acc[0] += r * r + im * im;
    }
    gPp[(ch * B * S + bs) * N + n] =
        ((acc[0] + acc[1]) + (acc[2] + acc[3])) + ((acc[4] + acc[5]) + (acc[6] + acc[7]));
}

__global__ void __launch_bounds__(128) k_psY() {
    const int tid = threadIdx.x;
    if (tid >= 125) return;
    const int n = blockIdx.x * 125 + tid;
    const int bs = blockIdx.y;
    const int ch = blockIdx.z;
    const float2* py = gY + (size_t)bs * F * N + n;
    const int f0 = ch * FCH;
    const int nf = ((f0 + FCH <= F) ? FCH : F - f0);
    float acc[8];
#pragma unroll
    for (int j = 0; j < 8; j++) acc[j] = 0.f;
    const int full = nf & ~7;
#pragma unroll 1
    for (int fb = 0; fb < full; fb += 8) {
        float2 v[8];
#pragma unroll
        for (int j = 0; j < 8; j++) v[j] = py[(size_t)(f0 + fb + j) * N];
#pragma unroll
        for (int j = 0; j < 8; j++) acc[j] += v[j].x * v[j].x + v[j].y * v[j].y;
    }
    for (int f = full; f < nf; f++) {
        float2 v = py[(size_t)(f0 + f) * N];
        acc[0] += v.x * v.x + v.y * v.y;
    }
    gPp[(ch * B * S + bs) * N + n] =
        ((acc[0] + acc[1]) + (acc[2] + acc[3])) + ((acc[4] + acc[5]) + (acc[6] + acc[7]));
}

__global__ void __launch_bounds__(256) k_wt() {
    const int bs = blockIdx.x;
    const int tid = threadIdx.x;
    float p[4];
    float s = 0.f;
#pragma unroll
    for (int i = 0; i < 4; i++) {
        int n = tid + i * 256;
        float acc = 0.f;
        if (n < N) {
#pragma unroll
            for (int ch = 0; ch < NCH; ch++) acc += gPp[(ch * B * S + bs) * N + n];
        }
        p[i] = acc;
        s += acc;
    }
    __shared__ float rr[8];
    __shared__ float g_sh;
#pragma unroll
    for (int off = 16; off > 0; off >>= 1) s += __shfl_down_sync(0xffffffffu, s, off);
    if ((tid & 31) == 0) rr[tid >> 5] = s;
    __syncthreads();
    if (tid == 0) {
        float tot = 0.f;
        for (int w = 0; w < 8; w++) tot += rr[w];
        float g = fmaxf(tot / (float)(F * N), EPS);
        g_sh = g;
        gGs[bs] = sqrtf(g);
    }
    __syncthreads();
    float g = g_sh;
#pragma unroll
    for (int i = 0; i < 4; i++) {
        int n = tid + i * 256;
        if (n < N) gWt[bs * N + n] = g / fmaxf(2.f * sqrtf(p[i]), MODEL_EPS);
    }
}

// ===========================================================================
// k_first: covariances + iteration 1
// ===========================================================================
__global__ void __launch_bounds__(NT, 4) k_first(const float* __restrict__ Xr,
                                                 const float* __restrict__ Xi) {
    extern __shared__ float2 sm1[];
    float2* Xs   = sm1;
    float2* sW   = Xs + C * ROW;
    float2* sH   = sW + S * C;
    float2* sJ   = sH + S * C * T;
    float2* sA   = sJ + CB * S;
    float2* sXX  = sA + S * C;
    float2* sXbX = sXX + C * C;
    float2* sv   = sXbX + C * T * C;            // 2
    u64*    red64 = (u64*)(sv + 2);             // 96 u64

    const int bf = blockIdx.x;
    const int b = bf / F, f = bf % F;
    const int tid = threadIdx.x;
    const int warp = tid >> 5, lane = tid & 31;

    load_Xpad(Xs, Xr, Xi, b, f, tid);

    const float i0 = 1.f / gGs[b * S + 0];
    const float i1 = 1.f / gGs[b * S + 1];

    if (tid < S * C) {
        int s = tid / C, c = tid % C;
        sW[tid] = make_float2((s == c) ? ((s == 0) ? i0 : i1) : 0.f, 0.f);
    }
    if (tid < S * C * T) sH[tid] = make_float2(0.f, 0.f);
    __syncthreads();

#define ACCP(j, A, Bv) { ar[j] += (A).x*(Bv).x + (A).y*(Bv).y; \
                         ai[j] += (A).y*(Bv).x - (A).x*(Bv).y; }
#pragma unroll 1
    for (int g = warp; g < 18; g += NT / 32) {
        int d = g / 3, p = g % 3, c0 = 2 * p;
        const float2* ad = Xs + d * ROW;
        const float2* b0 = Xs + c0 * ROW + PAD;
        const float2* b1 = b0 + ROW;
        float ar[12], ai[12];
#pragma unroll
        for (int j = 0; j < 12; j++) { ar[j] = 0.f; ai[j] = 0.f; }
        for (int n = lane; n < N; n += 32) {
            float2 a0 = ad[n], a1 = ad[n+1], a2 = ad[n+2], a3 = ad[n+3], a4 = ad[n+4];
            float2 a6 = ad[n+6];
            float2 u = b0[n], v = b1[n];
            ACCP(0, a0, u); ACCP(1, a1, u); ACCP(2, a2, u); ACCP(3, a3, u); ACCP(4, a4, u);
            ACCP(5, a0, v); ACCP(6, a1, v); ACCP(7, a2, v); ACCP(8, a3, v); ACCP(9, a4, v);
            ACCP(10, u, a6); ACCP(11, v, a6);
        }
#pragma unroll
        for (int off = 16; off > 0; off >>= 1)
#pragma unroll
            for (int j = 0; j < 12; j++) {
                ar[j] += __shfl_down_sync(0xffffffffu, ar[j], off);
                ai[j] += __shfl_down_sync(0xffffffffu, ai[j], off);
            }
        if (lane == 0) {
            const float invN = 1.f / (float)N;
#pragma unroll
            for (int t = 0; t < T; t++) {
                float2 v0 = make_float2(ar[t] * invN, ai[t] * invN);
                float2 v1 = make_float2(ar[5 + t] * invN, ai[5 + t] * invN);
                sXbX[(d * T + t) * C + c0]     = v0;
                sXbX[(d * T + t) * C + c0 + 1] = v1;
                gCXbX[bf * C * T * C + (d * T + t) * C + c0]     = v0;
                gCXbX[bf * C * T * C + (d * T + t) * C + c0 + 1] = v1;
            }
            float2 x0 = make_float2(ar[10] * invN, ai[10] * invN);
            float2 x1 = make_float2(ar[11] * invN, ai[11] * invN);
            sXX[c0 * C + d]       = x0;
            sXX[(c0 + 1) * C + d] = x1;
            gCXX[bf * C * C + c0 * C + d]       = x0;
            gCXX[bf * C * C + (c0 + 1) * C + d] = x1;
        }
    }
#undef ACCP

    u64 ya[4], yb[4], w01[4];
#pragma unroll
    for (int i = 0; i < 4; i++) {
        int n = tid + i * NT;
        if (n < N) {
            float2 a = Xs[0 * ROW + PAD + n];
            float2 c = Xs[1 * ROW + PAD + n];
            ya[i] = pk2(a.x * i0, c.x * i1);
            yb[i] = pk2(a.y * i0, c.y * i1);
            w01[i] = pk2(gWt[(b * S + 0) * N + n], gWt[(b * S + 1) * N + n]);
        } else {
            ya[i] = yb[i] = w01[i] = 0ull;
        }
    }
    __syncthreads();

    bg_update(sW, sH, sXX, sXbX, sA, tid);
    __syncthreads();
    if (tid == 0) solveJ(sA, sJ);
    __syncthreads();

    run_steps(Xs, sW, sH, sJ, red64, sv, ya, yb, w01, tid, warp, lane);
    __syncthreads();

#pragma unroll
    for (int i = 0; i < 4; i++) {
        int n = tid + i * NT;
        if (n < N) {
            float a, c, bb, d;
            up2(ya[i], a, c);
            up2(yb[i], bb, d);
            gY[((b * S + 0) * F + f) * N + n] = make_float2(a, bb);
            gY[((b * S + 1) * F + f) * N + n] = make_float2(c, d);
        }
    }
    if (tid < S * C) gW[bf * S * C + tid] = sW[tid];
    if (tid < S * C * T) gH[bf * S * C * T + tid] = sH[tid];
}

// ===========================================================================
// k_last: iteration 2 + final J + demix/derev + projection back + output
// ===========================================================================
__global__ void __launch_bounds__(NT, 4) k_last(const float* __restrict__ Xr,
                                                const float* __restrict__ Xi,
                                                float* __restrict__ out) {
    extern __shared__ float2 sm2[];
    float2* Xs   = sm2;
    float2* sW   = Xs + C * ROW;
    float2* sH   = sW + S * C;
    float2* sJ   = sH + S * C * T;
    float2* sA   = sJ + CB * S;
    float2* sXX  = sA + S * C;
    float2* sXbX = sXX + C * C;
    float2* sv   = sXbX + C * T * C;
    u64*    red64 = (u64*)(sv + 2);

    const int bf = blockIdx.x;
    const int b = bf / F, f = bf % F;
    const int tid = threadIdx.x;
    const int warp = tid >> 5, lane = tid & 31;

    load_Xpad(Xs, Xr, Xi, b, f, tid);

    const float i0 = 1.f / gGs[b * S + 0];
    const float i1 = 1.f / gGs[b * S + 1];

    if (tid < S * C) {
        float iv = (tid < C) ? i0 : i1;
        float2 w = gW[bf * S * C + tid];
        sW[tid] = make_float2(w.x * iv, w.y * iv);
    }
    if (tid < S * C * T) {
        float iv = (tid < C * T) ? i0 : i1;
        float2 h = gH[bf * S * C * T + tid];
        sH[tid] = make_float2(h.x * iv, h.y * iv);
    }
    if (tid < C * C) sXX[tid] = gCXX[bf * C * C + tid];
    if (tid < C * T * C) sXbX[tid] = gCXbX[bf * C * T * C + tid];

    u64 ya[4], yb[4], w01[4];
#pragma unroll
    for (int i = 0; i < 4; i++) {
        int n = tid + i * NT;
        if (n < N) {
            float2 a = gY[((b * S + 0) * F + f) * N + n];
            float2 c = gY[((b * S + 1) * F + f) * N + n];
            ya[i] = pk2(a.x * i0, c.x * i1);
            yb[i] = pk2(a.y * i0, c.y * i1);
            w01[i] = pk2(gWt[(b * S + 0) * N + n], gWt[(b * S + 1) * N + n]);
        } else {
            ya[i] = yb[i] = w01[i] = 0ull;
        }
    }
    __syncthreads();

    bg_update(sW, sH, sXX, sXbX, sA, tid);
    __syncthreads();
    if (tid == 0) solveJ(sA, sJ);
    __syncthreads();

    run_steps(Xs, sW, sH, sJ, red64, sv, ya, yb, w01, tid, warp, lane);
    __syncthreads();

    bg_update(sW, sH, sXX, sXbX, sA, tid);
    __syncthreads();
    if (tid == 0) {
        solveJ(sA, sJ);
        float2 Bm[2][2];
#pragma unroll
        for (int s = 0; s < S; s++)
#pragma unroll
            for (int k = 0; k < S; k++) {
                float2 acc = sW[s * C + k];
                for (int c = 0; c < CB; c++)
                    acc = cadd(acc, cmul(sW[s * C + S + c], sJ[c * S + k]));
                Bm[s][k] = acc;
            }
        float2 P00 = make_float2(Bm[0][0].x + PB_EPS, Bm[0][0].y);
        float2 P01 = Bm[1][0];
        float2 P10 = Bm[0][1];
        float2 P11 = make_float2(Bm[1][1].x + PB_EPS, Bm[1][1].y);
        float2 pdet = csub(cmul(P00, P11), cmul(P01, P10));
        sA[0] = cdiv(P11, pdet);
        sA[1] = cdiv(make_float2(-P10.x, -P10.y), pdet);
    }
    __syncthreads();

    float2 a0 = sA[0], a1 = sA[1];
    for (int n = tid; n < N; n += NT) {
#pragma unroll
        for (int s = 0; s < S; s++) {
            float2 y = make_float2(0.f, 0.f);
            for (int d = 0; d < C; d++) {
                const float2* xr = Xs + d * ROW + n;
                y = cadd(y, cmul(sW[s * C + d], xr[PAD]));
#pragma unroll
                for (int t = 0; t < T; t++)
                    y = csub(y, cmul(sH[(s * C + d) * T + t], xr[t]));
            }
            y = cmul(y, (s == 0) ? a0 : a1);
            size_t oi = ((size_t)((b * S + s) * F + f) * N + n) * 2;
            out[oi]     = y.x;
            out[oi + 1] = y.y;
        }
    }
}

// ===========================================================================
// launch
// ===========================================================================
namespace {
constexpr size_t SMEM_MAIN = sizeof(float2) * (size_t)(C * ROW + S * C + S * C * T +
                                                       CB * S + S * C + C * C + C * T * C + 2)
                           + sizeof(u64) * 96;
}

extern "C" void kernel_launch(void* const* d_in, const int* in_sizes, int n_in,
                              void* d_out, int out_size) {
    (void)in_sizes; (void)n_in; (void)out_size;
    const float* Xr = (const float*)d_in[0];
    const float* Xi = (const float*)d_in[1];
    float* out = (float*)d_out;

    cudaFuncSetAttribute(k_first, cudaFuncAttributeMaxDynamicSharedMemorySize, (int)SMEM_MAIN);
    cudaFuncSetAttribute(k_last,  cudaFuncAttributeMaxDynamicSharedMemorySize, (int)SMEM_MAIN);

    k_ps0<<<dim3(8, B * S, NCH), 128>>>(Xr, Xi);
    k_wt<<<B * S, 256>>>();
    k_first<<<NBF, NT, SMEM_MAIN>>>(Xr, Xi);
    k_psY<<<dim3(8, B * S, NCH), 128>>>();
    k_wt<<<B * S, 256>>>();
    k_last<<<NBF, NT, SMEM_MAIN>>>(Xr, Xi, out);
}

// round 14
// speedup vs baseline: 2.0222x; 1.0319x over previous
#include <cuda_runtime.h>

// ---------------------------------------------------------------------------
// OverISS_T, R14: R13 (=R9 baseline, 177-178us) with ONE isolated change:
// shortened warp0 mid — fast-math reciprocal/rsqrt for v, and 4-way smem
// gather + 3-stage packed shuffle instead of 5-stage. Hot loop untouched.
// ---------------------------------------------------------------------------

#define DEVFN __device__ __forceinline__
typedef unsigned long long u64;

namespace cfg {
constexpr int B = 2, C = 6, S = 2, F = 257, N = 1000, T = 5;
constexpr int CB = C - S;
constexpr int PAD = 6;
constexpr int ROW = 1032;
constexpr int NBF = B * F;
constexpr int NT = 256;
constexpr int NCH = 16;
constexpr int FCH = 17;
constexpr float EPS = 1e-3f;
constexpr float MODEL_EPS = 1e-5f;
constexpr float PB_EPS = 1e-6f;
}
using namespace cfg;

// ------------------------- global scratch -------------------------
__device__ float2 gY[B * S * F * N];
__device__ float2 gW[B * F * S * C];
__device__ float2 gH[B * F * S * C * T];
__device__ float2 gCXX[B * F * C * C];
__device__ float2 gCXbX[B * F * C * T * C];
__device__ float  gWt[B * S * N];
__device__ float  gPp[NCH * B * S * N];
__device__ float  gGs[B * S];

// ------------------------- complex helpers -------------------------
DEVFN float2 cmul(float2 a, float2 b) { return make_float2(a.x*b.x - a.y*b.y, a.x*b.y + a.y*b.x); }
DEVFN float2 cadd(float2 a, float2 b) { return make_float2(a.x + b.x, a.y + b.y); }
DEVFN float2 csub(float2 a, float2 b) { return make_float2(a.x - b.x, a.y - b.y); }
DEVFN float2 conjf2(float2 a)         { return make_float2(a.x, -a.y); }
DEVFN float2 cdiv(float2 a, float2 b) {
    float d = b.x*b.x + b.y*b.y;
    return make_float2((a.x*b.x + a.y*b.y) / d, (a.y*b.x - a.x*b.y) / d);
}

// ------------------------- packed f32x2 helpers (sm_103a) -------------------------
DEVFN u64 pk2(float lo, float hi) {
    u64 r; asm("mov.b64 %0, {%1, %2};" : "=l"(r) : "f"(lo), "f"(hi)); return r;
}
DEVFN void up2(u64 v, float& lo, float& hi) {
    asm("mov.b64 {%0, %1}, %2;" : "=f"(lo), "=f"(hi) : "l"(v));
}
DEVFN u64 f2mul(u64 a, u64 b) {
    u64 r; asm("mul.rn.f32x2 %0, %1, %2;" : "=l"(r) : "l"(a), "l"(b)); return r;
}
DEVFN u64 f2fma(u64 a, u64 b, u64 c) {
    u64 r; asm("fma.rn.f32x2 %0, %1, %2, %3;" : "=l"(r) : "l"(a), "l"(b), "l"(c)); return r;
}
DEVFN u64 f2add(u64 a, u64 b) {
    u64 r; asm("add.rn.f32x2 %0, %1, %2;" : "=l"(r) : "l"(a), "l"(b)); return r;
}
DEVFN u64 shfl64(u64 v, int off) {
    return __shfl_down_sync(0xffffffffu, v, off);
}

DEVFN void load_Xpad(float2* Xs, const float* __restrict__ Xr,
                     const float* __restrict__ Xi, int b, int f, int tid) {
    for (int i = tid; i < C * ROW; i += NT) {
        int d = i / ROW, j = i % ROW;
        float2 v = make_float2(0.f, 0.f);
        if (j >= PAD && j < PAD + N) {
            int gi = ((b * C + d) * F + f) * N + (j - PAD);
            v = make_float2(Xr[gi], Xi[gi]);
        }
        Xs[i] = v;
    }
}

DEVFN void bg_update(const float2* sW, const float2* sH, const float2* sXX,
                     const float2* sXbX, float2* sA, int tid) {
    if (tid < S * C) {
        int s = tid / C, d = tid % C;
        float2 acc = make_float2(0.f, 0.f);
        for (int c = 0; c < C; c++) acc = cadd(acc, cmul(sW[s * C + c], sXX[c * C + d]));
        for (int dd = 0; dd < C; dd++)
#pragma unroll
            for (int t = 0; t < T; t++)
                acc = cadd(acc, cmul(sH[(s * C + dd) * T + t], sXbX[(dd * T + t) * C + d]));
        sA[s * C + d] = acc;
    }
}

DEVFN void solveJ(const float2* sA, float2* sJ) {
    float2 M00 = sA[0], M01 = sA[1], M10 = sA[C], M11 = sA[C + 1];
    float2 det = csub(cmul(M00, M11), cmul(M01, M10));
#pragma unroll
    for (int k = 0; k < CB; k++) {
        float2 r0 = sA[2 + k], r1 = sA[C + 2 + k];
        float2 jh0 = cdiv(csub(cmul(M11, r0), cmul(M01, r1)), det);
        float2 jh1 = cdiv(csub(cmul(M00, r1), cmul(M10, r0)), det);
        sJ[k * S + 0] = conjf2(jh0);
        sJ[k * S + 1] = conjf2(jh1);
    }
}

// One ISS step on source-packed Y. Packed 3-stage warp reduce, lanes 0-3
// store u64 partials; warp0 mid: 4-way gather + 3-stage packed shuffle,
// fast-math reciprocal/rsqrt for v.
template <int MODE>
DEVFN void iss_core(const float2 (&xv)[4], u64 (&ya)[4], u64 (&yb)[4],
                    const u64 (&w01)[4],
                    float2* sW, float2* sH, const float2* sJ,
                    u64* red64, float2* sv,
                    int tid, int warp, int lane, int idx) {
    u64 s03 = 0ull, s14 = 0ull, s25 = 0ull;
#pragma unroll
    for (int i = 0; i < 4; i++) {
        float2 x = xv[i];
        u64 xx = pk2(x.x, x.x);
        u64 xy = pk2(x.y, x.y);
        float nx = -x.y;
        u64 nxy = pk2(nx, nx);
        u64 re = f2fma(yb[i], xy, f2mul(ya[i], xx));
        u64 im = f2fma(ya[i], nxy, f2mul(yb[i], xx));
        s03 = f2fma(w01[i], re, s03);
        s14 = f2fma(w01[i], im, s14);
        float mm = fmaf(x.y, x.y, x.x * x.x);
        s25 = f2fma(w01[i], pk2(mm, mm), s25);
    }
#pragma unroll
    for (int off = 16; off >= 4; off >>= 1) {
        s03 = f2add(s03, shfl64(s03, off));
        s14 = f2add(s14, shfl64(s14, off));
        s25 = f2add(s25, shfl64(s25, off));
    }
    if (lane < 4) {
        int slot = warp * 4 + lane;
        red64[0 * 32 + slot] = s03;
        red64[1 * 32 + slot] = s14;
        red64[2 * 32 + slot] = s25;
    }
    __syncthreads();
    if (warp == 0) {
        const int l8 = lane & 7;
        u64 a = f2add(f2add(red64[l8],      red64[l8 + 8]),
                      f2add(red64[l8 + 16], red64[l8 + 24]));
        u64 b = f2add(f2add(red64[32 + l8], red64[40 + l8]),
                      f2add(red64[48 + l8], red64[56 + l8]));
        u64 c = f2add(f2add(red64[64 + l8], red64[72 + l8]),
                      f2add(red64[80 + l8], red64[88 + l8]));
#pragma unroll
        for (int off = 4; off >= 1; off >>= 1) {
            a = f2add(a, shfl64(a, off));
            b = f2add(b, shfl64(b, off));
            c = f2add(c, shfl64(c, off));
        }
        if (lane == 0) {
            float t0, t1, t2, t3, t4, t5;
            up2(a, t0, t3); up2(b, t1, t4); up2(c, t2, t5);
            if (MODE == 0) {
                const float invN = 1.f / (float)N;
                t0 *= invN; t1 *= invN; t2 *= invN;
                t3 *= invN; t4 *= invN; t5 *= invN;
            }
            float inv0 = __fdividef(1.f, fmaxf(t2, EPS));
            float inv1 = __fdividef(1.f, fmaxf(t5, EPS));
            float2 v0 = make_float2(t0 * inv0, t1 * inv0);
            float2 v1 = make_float2(t3 * inv1, t4 * inv1);
            if (MODE == 0) {
                float ds = (idx == 0) ? t2 : t5;
                float vs = 1.f - rsqrtf(fmaxf(ds, EPS));
                if (idx == 0) v0 = make_float2(vs, 0.f);
                else          v1 = make_float2(vs, 0.f);
            }
            sv[0] = v0; sv[1] = v1;
        }
    }
    __syncthreads();
    float2 v0 = sv[0], v1 = sv[1];
    u64 nvx = pk2(-v0.x, -v1.x);
    u64 vvy = pk2(v0.y, v1.y);
    u64 nvy = pk2(-v0.y, -v1.y);
#pragma unroll
    for (int i = 0; i < 4; i++) {
        float2 x = xv[i];
        u64 xx = pk2(x.x, x.x);
        u64 xy = pk2(x.y, x.y);
        ya[i] = f2fma(vvy, xy, f2fma(nvx, xx, ya[i]));
        yb[i] = f2fma(nvy, xx, f2fma(nvx, xy, yb[i]));
    }
    if (MODE == 0) {
        if (tid < C) {
            float2 a = sW[idx * C + tid];
            sW[tid]     = csub(sW[tid],     cmul(v0, a));
            sW[C + tid] = csub(sW[C + tid], cmul(v1, a));
        } else if (tid >= 32 && tid < 32 + C * T) {
            int j = tid - 32;
            float2 a = sH[idx * C * T + j];
            sH[j]         = csub(sH[j],         cmul(v0, a));
            sH[C * T + j] = csub(sH[C * T + j], cmul(v1, a));
        }
    } else if (MODE == 1) {
        if (tid < 2) {
            float2 v = tid ? v1 : v0;
            sW[tid * C + 0]       = csub(sW[tid * C + 0], cmul(v, sJ[idx * S + 0]));
            sW[tid * C + 1]       = csub(sW[tid * C + 1], cmul(v, sJ[idx * S + 1]));
            sW[tid * C + S + idx] = cadd(sW[tid * C + S + idx], v);
        }
    } else {
        if (tid < 2) {
            float2 v = tid ? v1 : v0;
            int d = idx / T, tp = idx % T;
            sH[(tid * C + d) * T + tp] = cadd(sH[(tid * C + d) * T + tp], v);
        }
    }
}

DEVFN void run_steps(const float2* Xs, float2* sW, float2* sH, const float2* sJ,
                     u64* red64, float2* sv, u64 (&ya)[4], u64 (&yb)[4],
                     const u64 (&w01)[4],
                     int tid, int warp, int lane) {
#pragma unroll 1
    for (int src = 0; src < S; src++) {
        float2 xv[4];
#pragma unroll
        for (int i = 0; i < 4; i++) {
            float a, c, bb, d;
            up2(ya[i], a, c);
            up2(yb[i], bb, d);
            xv[i] = src ? make_float2(c, d) : make_float2(a, bb);
        }
        iss_core<0>(xv, ya, yb, w01, sW, sH, sJ, red64, sv, tid, warp, lane, src);
    }
#pragma unroll 1
    for (int k = 0; k < CB; k++) {
        float2 j0 = sJ[k * S + 0], j1 = sJ[k * S + 1];
        float2 xv[4];
#pragma unroll
        for (int i = 0; i < 4; i++) {
            int n = tid + i * NT;
            float2 x0 = Xs[0 * ROW + PAD + n];
            float2 x1 = Xs[ROW + PAD + n];
            float2 xb = Xs[(S + k) * ROW + PAD + n];
            xv[i] = csub(cadd(cmul(j0, x0), cmul(j1, x1)), xb);
        }
        iss_core<1>(xv, ya, yb, w01, sW, sH, sJ, red64, sv, tid, warp, lane, k);
    }
#pragma unroll 1
    for (int q = 0; q < C * T; q++) {
        const float2* xp = Xs + (q / T) * ROW + (q % T);
        float2 xv[4];
#pragma unroll
        for (int i = 0; i < 4; i++) xv[i] = xp[tid + i * NT];
        iss_core<2>(xv, ya, yb, w01, sW, sH, sJ, red64, sv, tid, warp, lane, q);
    }
}

// ===========================================================================
// Weight reduction: NCH f-chunks, MLP-8 batched loads
// ===========================================================================
__global__ void __launch_bounds__(128) k_ps0(const float* __restrict__ Xr,
                                             const float* __restrict__ Xi) {
    const int tid = threadIdx.x;
    if (tid >= 125) return;
    const int n = blockIdx.x * 125 + tid;
    const int bs = blockIdx.y;
    const int ch = blockIdx.z;
    const int b = bs / S, s = bs % S;
    const size_t base = ((size_t)(b * C + s) * F) * N + n;
    const int f0 = ch * FCH;
    const int nf = ((f0 + FCH <= F) ? FCH : F - f0);
    float acc[8];
#pragma unroll
    for (int j = 0; j < 8; j++) acc[j] = 0.f;
    const int full = nf & ~7;
#pragma unroll 1
    for (int fb = 0; fb < full; fb += 8) {
        float r[8], im[8];
#pragma unroll
        for (int j = 0; j < 8; j++) {
            size_t p = base + (size_t)(f0 + fb + j) * N;
            r[j] = Xr[p];
            im[j] = Xi[p];
        }
#pragma unroll
        for (int j = 0; j < 8; j++) acc[j] += r[j] * r[j] + im[j] * im[j];
    }
    for (int f = full; f < nf; f++) {
        size_t p = base + (size_t)(f0 + f) * N;
        float r = Xr[p], im = Xi[p];
        acc[0] += r * r + im * im;
    }
    gPp[(ch * B * S + bs) * N + n] =
        ((acc[0] + acc[1]) + (acc[2] + acc[3])) + ((acc[4] + acc[5]) + (acc[6] + acc[7]));
}

__global__ void __launch_bounds__(128) k_psY() {
    const int tid = threadIdx.x;
    if (tid >= 125) return;
    const int n = blockIdx.x * 125 + tid;
    const int bs = blockIdx.y;
    const int ch = blockIdx.z;
    const float2* py = gY + (size_t)bs * F * N + n;
    const int f0 = ch * FCH;
    const int nf = ((f0 + FCH <= F) ? FCH : F - f0);
    float acc[8];
#pragma unroll
    for (int j = 0; j < 8; j++) acc[j] = 0.f;
    const int full = nf & ~7;
#pragma unroll 1
    for (int fb = 0; fb < full; fb += 8) {
        float2 v[8];
#pragma unroll
        for (int j = 0; j < 8; j++) v[j] = py[(size_t)(f0 + fb + j) * N];
#pragma unroll
        for (int j = 0; j < 8; j++) acc[j] += v[j].x * v[j].x + v[j].y * v[j].y;
    }
    for (int f = full; f < nf; f++) {
        float2 v = py[(size_t)(f0 + f) * N];
        acc[0] += v.x * v.x + v.y * v.y;
    }
    gPp[(ch * B * S + bs) * N + n] =
        ((acc[0] + acc[1]) + (acc[2] + acc[3])) + ((acc[4] + acc[5]) + (acc[6] + acc[7]));
}

__global__ void __launch_bounds__(256) k_wt() {
    const int bs = blockIdx.x;
    const int tid = threadIdx.x;
    float p[4];
    float s = 0.f;
#pragma unroll
    for (int i = 0; i < 4; i++) {
        int n = tid + i * 256;
        float acc = 0.f;
        if (n < N) {
#pragma unroll
            for (int ch = 0; ch < NCH; ch++) acc += gPp[(ch * B * S + bs) * N + n];
        }
        p[i] = acc;
        s += acc;
    }
    __shared__ float rr[8];
    __shared__ float g_sh;
#pragma unroll
    for (int off = 16; off > 0; off >>= 1) s += __shfl_down_sync(0xffffffffu, s, off);
    if ((tid & 31) == 0) rr[tid >> 5] = s;
    __syncthreads();
    if (tid == 0) {
        float tot = 0.f;
        for (int w = 0; w < 8; w++) tot += rr[w];
        float g = fmaxf(tot / (float)(F * N), EPS);
        g_sh = g;
        gGs[bs] = sqrtf(g);
    }
    __syncthreads();
    float g = g_sh;
#pragma unroll
    for (int i = 0; i < 4; i++) {
        int n = tid + i * 256;
        if (n < N) gWt[bs * N + n] = g / fmaxf(2.f * sqrtf(p[i]), MODEL_EPS);
    }
}

// ===========================================================================
// k_first: covariances + iteration 1
// ===========================================================================
__global__ void __launch_bounds__(NT, 4) k_first(const float* __restrict__ Xr,
                                                 const float* __restrict__ Xi) {
    extern __shared__ float2 sm1[];
    float2* Xs   = sm1;
    float2* sW   = Xs + C * ROW;
    float2* sH   = sW + S * C;
    float2* sJ   = sH + S * C * T;
    float2* sA   = sJ + CB * S;
    float2* sXX  = sA + S * C;
    float2* sXbX = sXX + C * C;
    float2* sv   = sXbX + C * T * C;            // 2
    u64*    red64 = (u64*)(sv + 2);             // 96 u64

    const int bf = blockIdx.x;
    const int b = bf / F, f = bf % F;
    const int tid = threadIdx.x;
    const int warp = tid >> 5, lane = tid & 31;

    load_Xpad(Xs, Xr, Xi, b, f, tid);

    const float i0 = 1.f / gGs[b * S + 0];
    const float i1 = 1.f / gGs[b * S + 1];

    if (tid < S * C) {
        int s = tid / C, c = tid % C;
        sW[tid] = make_float2((s == c) ? ((s == 0) ? i0 : i1) : 0.f, 0.f);
    }
    if (tid < S * C * T) sH[tid] = make_float2(0.f, 0.f);
    __syncthreads();

#define ACCP(j, A, Bv) { ar[j] += (A).x*(Bv).x + (A).y*(Bv).y; \
                         ai[j] += (A).y*(Bv).x - (A).x*(Bv).y; }
#pragma unroll 1
    for (int g = warp; g < 18; g += NT / 32) {
        int d = g / 3, p = g % 3, c0 = 2 * p;
        const float2* ad = Xs + d * ROW;
        const float2* b0 = Xs + c0 * ROW + PAD;
        const float2* b1 = b0 + ROW;
        float ar[12], ai[12];
#pragma unroll
        for (int j = 0; j < 12; j++) { ar[j] = 0.f; ai[j] = 0.f; }
        for (int n = lane; n < N; n += 32) {
            float2 a0 = ad[n], a1 = ad[n+1], a2 = ad[n+2], a3 = ad[n+3], a4 = ad[n+4];
            float2 a6 = ad[n+6];
            float2 u = b0[n], v = b1[n];
            ACCP(0, a0, u); ACCP(1, a1, u); ACCP(2, a2, u); ACCP(3, a3, u); ACCP(4, a4, u);
            ACCP(5, a0, v); ACCP(6, a1, v); ACCP(7, a2, v); ACCP(8, a3, v); ACCP(9, a4, v);
            ACCP(10, u, a6); ACCP(11, v, a6);
        }
#pragma unroll
        for (int off = 16; off > 0; off >>= 1)
#pragma unroll
            for (int j = 0; j < 12; j++) {
                ar[j] += __shfl_down_sync(0xffffffffu, ar[j], off);
                ai[j] += __shfl_down_sync(0xffffffffu, ai[j], off);
            }
        if (lane == 0) {
            const float invN = 1.f / (float)N;
#pragma unroll
            for (int t = 0; t < T; t++) {
                float2 v0 = make_float2(ar[t] * invN, ai[t] * invN);
                float2 v1 = make_float2(ar[5 + t] * invN, ai[5 + t] * invN);
                sXbX[(d * T + t) * C + c0]     = v0;
                sXbX[(d * T + t) * C + c0 + 1] = v1;
                gCXbX[bf * C * T * C + (d * T + t) * C + c0]     = v0;
                gCXbX[bf * C * T * C + (d * T + t) * C + c0 + 1] = v1;
            }
            float2 x0 = make_float2(ar[10] * invN, ai[10] * invN);
            float2 x1 = make_float2(ar[11] * invN, ai[11] * invN);
            sXX[c0 * C + d]       = x0;
            sXX[(c0 + 1) * C + d] = x1;
            gCXX[bf * C * C + c0 * C + d]       = x0;
            gCXX[bf * C * C + (c0 + 1) * C + d] = x1;
        }
    }
#undef ACCP

    u64 ya[4], yb[4], w01[4];
#pragma unroll
    for (int i = 0; i < 4; i++) {
        int n = tid + i * NT;
        if (n < N) {
            float2 a = Xs[0 * ROW + PAD + n];
            float2 c = Xs[1 * ROW + PAD + n];
            ya[i] = pk2(a.x * i0, c.x * i1);
            yb[i] = pk2(a.y * i0, c.y * i1);
            w01[i] = pk2(gWt[(b * S + 0) * N + n], gWt[(b * S + 1) * N + n]);
        } else {
            ya[i] = yb[i] = w01[i] = 0ull;
        }
    }
    __syncthreads();

    bg_update(sW, sH, sXX, sXbX, sA, tid);
    __syncthreads();
    if (tid == 0) solveJ(sA, sJ);
    __syncthreads();

    run_steps(Xs, sW, sH, sJ, red64, sv, ya, yb, w01, tid, warp, lane);
    __syncthreads();

#pragma unroll
    for (int i = 0; i < 4; i++) {
        int n = tid + i * NT;
        if (n < N) {
            float a, c, bb, d;
            up2(ya[i], a, c);
            up2(yb[i], bb, d);
            gY[((b * S + 0) * F + f) * N + n] = make_float2(a, bb);
            gY[((b * S + 1) * F + f) * N + n] = make_float2(c, d);
        }
    }
    if (tid < S * C) gW[bf * S * C + tid] = sW[tid];
    if (tid < S * C * T) gH[bf * S * C * T + tid] = sH[tid];
}

// ===========================================================================
// k_last: iteration 2 + final J + demix/derev + projection back + output
// ===========================================================================
__global__ void __launch_bounds__(NT, 4) k_last(const float* __restrict__ Xr,
                                                const float* __restrict__ Xi,
                                                float* __restrict__ out) {
    extern __shared__ float2 sm2[];
    float2* Xs   = sm2;
    float2* sW   = Xs + C * ROW;
    float2* sH   = sW + S * C;
    float2* sJ   = sH + S * C * T;
    float2* sA   = sJ + CB * S;
    float2* sXX  = sA + S * C;
    float2* sXbX = sXX + C * C;
    float2* sv   = sXbX + C * T * C;
    u64*    red64 = (u64*)(sv + 2);

    const int bf = blockIdx.x;
    const int b = bf / F, f = bf % F;
    const int tid = threadIdx.x;
    const int warp = tid >> 5, lane = tid & 31;

    load_Xpad(Xs, Xr, Xi, b, f, tid);

    const float i0 = 1.f / gGs[b * S + 0];
    const float i1 = 1.f / gGs[b * S + 1];

    if (tid < S * C) {
        float iv = (tid < C) ? i0 : i1;
        float2 w = gW[bf * S * C + tid];
        sW[tid] = make_float2(w.x * iv, w.y * iv);
    }
    if (tid < S * C * T) {
        float iv = (tid < C * T) ? i0 : i1;
        float2 h = gH[bf * S * C * T + tid];
        sH[tid] = make_float2(h.x * iv, h.y * iv);
    }
    if (tid < C * C) sXX[tid] = gCXX[bf * C * C + tid];
    if (tid < C * T * C) sXbX[tid] = gCXbX[bf * C * T * C + tid];

    u64 ya[4], yb[4], w01[4];
#pragma unroll
    for (int i = 0; i < 4; i++) {
        int n = tid + i * NT;
        if (n < N) {
            float2 a = gY[((b * S + 0) * F + f) * N + n];
            float2 c = gY[((b * S + 1) * F + f) * N + n];
            ya[i] = pk2(a.x * i0, c.x * i1);
            yb[i] = pk2(a.y * i0, c.y * i1);
            w01[i] = pk2(gWt[(b * S + 0) * N + n], gWt[(b * S + 1) * N + n]);
        } else {
            ya[i] = yb[i] = w01[i] = 0ull;
        }
    }
    __syncthreads();

    bg_update(sW, sH, sXX, sXbX, sA, tid);
    __syncthreads();
    if (tid == 0) solveJ(sA, sJ);
    __syncthreads();

    run_steps(Xs, sW, sH, sJ, red64, sv, ya, yb, w01, tid, warp, lane);
    __syncthreads();

    bg_update(sW, sH, sXX, sXbX, sA, tid);
    __syncthreads();
    if (tid == 0) {
        solveJ(sA, sJ);
        float2 Bm[2][2];
#pragma unroll
        for (int s = 0; s < S; s++)
#pragma unroll
            for (int k = 0; k < S; k++) {
                float2 acc = sW[s * C + k];
                for (int c = 0; c < CB; c++)
                    acc = cadd(acc, cmul(sW[s * C + S + c], sJ[c * S + k]));
                Bm[s][k] = acc;
            }
        float2 P00 = make_float2(Bm[0][0].x + PB_EPS, Bm[0][0].y);
        float2 P01 = Bm[1][0];
        float2 P10 = Bm[0][1];
        float2 P11 = make_float2(Bm[1][1].x + PB_EPS, Bm[1][1].y);
        float2 pdet = csub(cmul(P00, P11), cmul(P01, P10));
        sA[0] = cdiv(P11, pdet);
        sA[1] = cdiv(make_float2(-P10.x, -P10.y), pdet);
    }
    __syncthreads();

    float2 a0 = sA[0], a1 = sA[1];
    for (int n = tid; n < N; n += NT) {
#pragma unroll
        for (int s = 0; s < S; s++) {
            float2 y = make_float2(0.f, 0.f);
            for (int d = 0; d < C; d++) {
                const float2* xr = Xs + d * ROW + n;
                y = cadd(y, cmul(sW[s * C + d], xr[PAD]));
#pragma unroll
                for (int t = 0; t < T; t++)
                    y = csub(y, cmul(sH[(s * C + d) * T + t], xr[t]));
            }
            y = cmul(y, (s == 0) ? a0 : a1);
            size_t oi = ((size_t)((b * S + s) * F + f) * N + n) * 2;
            out[oi]     = y.x;
            out[oi + 1] = y.y;
        }
    }
}

// ===========================================================================
// launch
// ===========================================================================
namespace {
constexpr size_t SMEM_MAIN = sizeof(float2) * (size_t)(C * ROW + S * C + S * C * T +
                                                       CB * S + S * C + C * C + C * T * C + 2)
                           + sizeof(u64) * 96;
}

extern "C" void kernel_launch(void* const* d_in, const int* in_sizes, int n_in,
                              void* d_out, int out_size) {
    (void)in_sizes; (void)n_in; (void)out_size;
    const float* Xr = (const float*)d_in[0];
    const float* Xi = (const float*)d_in[1];
    float* out = (float*)d_out;

    cudaFuncSetAttribute(k_first, cudaFuncAttributeMaxDynamicSharedMemorySize, (int)SMEM_MAIN);
    cudaFuncSetAttribute(k_last,  cudaFuncAttributeMaxDynamicSharedMemorySize, (int)SMEM_MAIN);

    k_ps0<<<dim3(8, B * S, NCH), 128>>>(Xr, Xi);
    k_wt<<<B * S, 256>>>();
    k_first<<<NBF, NT, SMEM_MAIN>>>(Xr, Xi);
    k_psY<<<dim3(8, B * S, NCH), 128>>>();
    k_wt<<<B * S, 256>>>();
    k_last<<<NBF, NT, SMEM_MAIN>>>(Xr, Xi, out);
}